// round 5
// baseline (speedup 1.0000x reference)
#include <cuda_runtime.h>

// ChronoRotationTransflormation: per-row normalized complex inner product.
// Inputs (metadata order): head_real, head_imag, rel_real, rel_imag, tail_real, tail_imag
// all float32 [8192, 2048]. Output: float32 [8192].
//
// rot_r = hr*rr - hi*ri
// rot_i = -(hi*rr + hr*ri)
// ab = sum(rot_r*tr + rot_i*ti); aa = sum(rot_r^2+rot_i^2); bb = sum(tr^2+ti^2)
// out = ab / sqrt(aa*bb)

#define D 2048
#define DV (D / 4)          // 512 float4 per row
#define THREADS 256
#define WARPS (THREADS / 32)

__global__ __launch_bounds__(THREADS)
void chrono_rot_kernel(const float4* __restrict__ hr,
                       const float4* __restrict__ hi,
                       const float4* __restrict__ rr,
                       const float4* __restrict__ ri,
                       const float4* __restrict__ tr,
                       const float4* __restrict__ ti,
                       float* __restrict__ out)
{
    const int row = blockIdx.x;
    const long long base = (long long)row * DV;

    float ab = 0.f, aa = 0.f, bb = 0.f;

    // 512 float4 / 256 threads = 2 iterations; fully unrolled so all 12
    // LDG.128 are front-batched (high MLP).
    #pragma unroll
    for (int it = 0; it < DV / THREADS; ++it) {
        const int i = it * THREADS + threadIdx.x;
        const float4 HR = hr[base + i];
        const float4 HI = hi[base + i];
        const float4 RR = rr[base + i];
        const float4 RI = ri[base + i];
        const float4 TR = tr[base + i];
        const float4 TI = ti[base + i];

        #pragma unroll
        for (int k = 0; k < 4; ++k) {
            const float h_r = (&HR.x)[k], h_i = (&HI.x)[k];
            const float r_r = (&RR.x)[k], r_i = (&RI.x)[k];
            const float t_r = (&TR.x)[k], t_i = (&TI.x)[k];
            const float rot_r = h_r * r_r - h_i * r_i;
            const float rot_i = -(h_i * r_r + h_r * r_i);
            ab = fmaf(rot_r, t_r, fmaf(rot_i, t_i, ab));
            aa = fmaf(rot_r, rot_r, fmaf(rot_i, rot_i, aa));
            bb = fmaf(t_r, t_r, fmaf(t_i, t_i, bb));
        }
    }

    // Warp reduction (butterfly)
    #pragma unroll
    for (int off = 16; off > 0; off >>= 1) {
        ab += __shfl_xor_sync(0xFFFFFFFFu, ab, off);
        aa += __shfl_xor_sync(0xFFFFFFFFu, aa, off);
        bb += __shfl_xor_sync(0xFFFFFFFFu, bb, off);
    }

    __shared__ float s_ab[WARPS], s_aa[WARPS], s_bb[WARPS];
    const int wid = threadIdx.x >> 5;
    const int lid = threadIdx.x & 31;
    if (lid == 0) {
        s_ab[wid] = ab;
        s_aa[wid] = aa;
        s_bb[wid] = bb;
    }
    __syncthreads();

    if (threadIdx.x == 0) {
        float tab = 0.f, taa = 0.f, tbb = 0.f;
        #pragma unroll
        for (int w = 0; w < WARPS; ++w) {
            tab += s_ab[w];
            taa += s_aa[w];
            tbb += s_bb[w];
        }
        out[row] = tab / sqrtf(taa * tbb);
    }
}

extern "C" void kernel_launch(void* const* d_in, const int* in_sizes, int n_in,
                              void* d_out, int out_size)
{
    const float4* hr = (const float4*)d_in[0];
    const float4* hi = (const float4*)d_in[1];
    const float4* rr = (const float4*)d_in[2];
    const float4* ri = (const float4*)d_in[3];
    const float4* tr = (const float4*)d_in[4];
    const float4* ti = (const float4*)d_in[5];
    float* out = (float*)d_out;

    const int rows = out_size;  // 8192
    chrono_rot_kernel<<<rows, THREADS>>>(hr, hi, rr, ri, tr, ti, out);
}